// round 10
// baseline (speedup 1.0000x reference)
#include <cuda_runtime.h>
#include <math.h>

// Problem constants (fixed by reference: H = W = 2048)
#define H_ 2048
#define W_ 2048
#define HW_ (H_ * W_)
#define LOG2W 11

// Packed direction indices (one byte per pixel), sobel -> nms. 4 MB scratch.
__device__ unsigned char g_q[HW_];

// ---------------------------------------------------------------------------
// Kernel 1: FUSED gaussian blur (1x5 + 5x1, zero pad 2) + sobel + grad_mag +
// orient + early_threshold, per 128x16 tile, all 3 channels in one block.
//
// Per channel: h-pass -> hA smem (22 x 34 float4), v-pass -> per-channel
// blurred tile (18 x 34 float4; includes the +-1 sobel halo; rows/cols outside
// the image stored as 0 == reference zero padding) + central 128x16 written to
// gmem blurred. Then sobel runs entirely from the smem tiles.
// All arithmetic chains identical to prior rounds (bit-exact).
// ---------------------------------------------------------------------------
#define FTX 128
#define FTY 16
#define NCU 34                 // float4 col units: cols x0-4 .. x0+131
#define HROWS (FTY + 6)        // 22: h rows y0-3 .. y0+18
#define VROWS (FTY + 2)        // 18: blurred rows y0-1 .. y0+16

__global__ void __launch_bounds__(256)
blur_sobel_k(const float* __restrict__ img, const float* __restrict__ g,
             const float* __restrict__ thr_p,
             float* __restrict__ blurred, float* __restrict__ grad,
             float* __restrict__ orient, float* __restrict__ early) {
    __shared__ float4 hA[HROWS][NCU];            // 11,968 B
    __shared__ float4 tile4[3][VROWS][NCU];      // 29,376 B
    const float* tileF = (const float*)tile4;

    const int x0 = blockIdx.x * FTX;
    const int y0 = blockIdx.y * FTY;
    const int t = threadIdx.x;                   // 0..255
    const float g0 = g[0], g1 = g[1], g2 = g[2], g3 = g[3], g4 = g[4];
    const float thr = __ldg(thr_p);
    const float4 z4 = make_float4(0.f, 0.f, 0.f, 0.f);

#pragma unroll
    for (int c = 0; c < 3; ++c) {
        const float* im = img + c * HW_;
        // ---- horizontal pass: 22 x 34 = 748 units ----
        for (int u = t; u < HROWS * NCU; u += 256) {
            int r = u / NCU;
            int j = u - r * NCU;
            int gy = y0 - 3 + r;
            int gx = x0 - 4 + 4 * j;
            float4 o = z4;
            if (gy >= 0 && gy < H_ && gx >= 0 && gx < W_) {
                const float4* row4 = (const float4*)(im + gy * W_);
                float4 L = (gx >= 4)     ? __ldg(row4 + (gx >> 2) - 1) : z4;
                float4 M =                 __ldg(row4 + (gx >> 2));
                float4 R = (gx + 4 < W_) ? __ldg(row4 + (gx >> 2) + 1) : z4;
                float v0 = L.z, v1 = L.w;
                float v2 = M.x, v3 = M.y, v4 = M.z, v5 = M.w;
                float v6 = R.x, v7 = R.y;
                o.x = fmaf(g4, v4, fmaf(g3, v3, fmaf(g2, v2, fmaf(g1, v1, __fmul_rn(g0, v0)))));
                o.y = fmaf(g4, v5, fmaf(g3, v4, fmaf(g2, v3, fmaf(g1, v2, __fmul_rn(g0, v1)))));
                o.z = fmaf(g4, v6, fmaf(g3, v5, fmaf(g2, v4, fmaf(g1, v3, __fmul_rn(g0, v2)))));
                o.w = fmaf(g4, v7, fmaf(g3, v6, fmaf(g2, v5, fmaf(g1, v4, __fmul_rn(g0, v3)))));
            }
            hA[r][j] = o;
        }
        __syncthreads();

        // ---- vertical pass: 18 x 34 = 612 units ----
        for (int u = t; u < VROWS * NCU; u += 256) {
            int r = u / NCU;
            int j = u - r * NCU;
            int gyp = y0 - 1 + r;
            float4 o = z4;
            if (gyp >= 0 && gyp < H_) {          // outside image -> 0 (sobel pad)
                float4 r0 = hA[r][j];
                float4 r1 = hA[r + 1][j];
                float4 r2 = hA[r + 2][j];
                float4 r3 = hA[r + 3][j];
                float4 r4 = hA[r + 4][j];
                o.x = fmaf(g4, r4.x, fmaf(g3, r3.x, fmaf(g2, r2.x, fmaf(g1, r1.x, __fmul_rn(g0, r0.x)))));
                o.y = fmaf(g4, r4.y, fmaf(g3, r3.y, fmaf(g2, r2.y, fmaf(g1, r1.y, __fmul_rn(g0, r0.y)))));
                o.z = fmaf(g4, r4.z, fmaf(g3, r3.z, fmaf(g2, r2.z, fmaf(g1, r1.z, __fmul_rn(g0, r0.z)))));
                o.w = fmaf(g4, r4.w, fmaf(g3, r3.w, fmaf(g2, r2.w, fmaf(g1, r1.w, __fmul_rn(g0, r0.w)))));
            }
            tile4[c][r][j] = o;
            // central 128x16 -> gmem blurred
            if (r >= 1 && r <= FTY && j >= 1 && j <= 32) {
                int gx = x0 - 4 + 4 * j;
                *(float4*)(blurred + c * HW_ + gyp * W_ + gx) = o;
            }
        }
        __syncthreads();   // tile complete; also protects hA for next channel
    }

    // ---- sobel + orient + early from smem tiles: 16 x 32 = 512 units ----
    const float C = (float)(180.0 / 3.14159);   // NOTE: 3.14159, not pi
    for (int v = t; v < FTY * 32; v += 256) {
        int ry = v >> 5;            // 0..15
        int ux = v & 31;            // 0..31
        int cs = 4 * ux + 4;        // tile col of pixel 0

        float mag[4] = {0.f, 0.f, 0.f, 0.f};
        float sx[4]  = {0.f, 0.f, 0.f, 0.f};
        float sy[4]  = {0.f, 0.f, 0.f, 0.f};
#pragma unroll
        for (int c = 0; c < 3; ++c) {
            const float* r0 = tileF + ((c * VROWS + ry    ) * NCU) * 4;
            const float* r1 = tileF + ((c * VROWS + ry + 1) * NCU) * 4;
            const float* r2 = tileF + ((c * VROWS + ry + 2) * NCU) * 4;
            float tp[6], md[6], bt[6];
            {
                float4 vv = *(const float4*)(r0 + cs);
                tp[1] = vv.x; tp[2] = vv.y; tp[3] = vv.z; tp[4] = vv.w;
                tp[0] = r0[cs - 1]; tp[5] = r0[cs + 4];
            }
            {
                float4 vv = *(const float4*)(r1 + cs);
                md[1] = vv.x; md[2] = vv.y; md[3] = vv.z; md[4] = vv.w;
                md[0] = r1[cs - 1]; md[5] = r1[cs + 4];
            }
            {
                float4 vv = *(const float4*)(r2 + cs);
                bt[1] = vv.x; bt[2] = vv.y; bt[3] = vv.z; bt[4] = vv.w;
                bt[0] = r2[cs - 1]; bt[5] = r2[cs + 4];
            }
#pragma unroll
            for (int i = 0; i < 4; ++i) {
                float a00 = tp[i], a01 = tp[i + 1], a02 = tp[i + 2];
                float a10 = md[i],                  a12 = md[i + 2];
                float a20 = bt[i], a21 = bt[i + 1], a22 = bt[i + 2];
                float gxx = a00;
                gxx = fmaf(-1.f, a02, gxx);
                gxx = fmaf( 2.f, a10, gxx);
                gxx = fmaf(-2.f, a12, gxx);
                gxx = fmaf( 1.f, a20, gxx);
                gxx = fmaf(-1.f, a22, gxx);
                float gyy = a00;
                gyy = fmaf( 2.f, a01, gyy);
                gyy = fmaf( 1.f, a02, gyy);
                gyy = fmaf(-1.f, a20, gyy);
                gyy = fmaf(-2.f, a21, gyy);
                gyy = fmaf(-1.f, a22, gyy);

                mag[i] = __fadd_rn(mag[i], sqrtf(fmaf(gxx, gxx, __fmul_rn(gyy, gyy))));
                sx[i]  = __fadd_rn(sx[i], gxx);
                sy[i]  = __fadd_rn(sy[i], gyy);
            }
        }

        float4 gm4, or4, ea4;
        float* gmA = (float*)&gm4;
        float* orA = (float*)&or4;
        float* eaA = (float*)&ea4;
        unsigned qpack = 0;
#pragma unroll
        for (int i = 0; i < 4; ++i) {
            float o  = atan2f(sy[i], sx[i]);     // libdevice __nv_atan2f (== XLA)
            float ov = __fmul_rn(o, C);
            float tt = __fdiv_rn(__fadd_rn(ov, 180.0f), 45.0f);
            float q  = rintf(tt);                // half-even (jnp.round)
            gmA[i] = mag[i];
            orA[i] = __fmul_rn(q, 45.0f);
            eaA[i] = (mag[i] < thr) ? 0.f : mag[i];
            qpack |= ((unsigned)(int)q) << (i * 8);   // q in [0,8]
        }
        int idx = (y0 + ry) * W_ + x0 + 4 * ux;
        *(float4*)(grad + idx)   = gm4;
        *(float4*)(orient + idx) = or4;
        *(float4*)(early + idx)  = ea4;
        *(unsigned*)(g_q + idx)  = qpack;
    }
}

// ---------------------------------------------------------------------------
// Kernel 2: NMS + threshold, 4 px/thread. Identical to R9 (bit-exact).
// dir k offsets (dy,dx): 0:(0,1) 1:(1,1) 2:(1,0) 3:(1,-1) 4:(0,-1)
//                        5:(-1,-1) 6:(-1,0) 7:(-1,1)
// ---------------------------------------------------------------------------
__global__ void nms_k(const float* __restrict__ grad,
                      const float* __restrict__ thr_p,
                      float* __restrict__ thin,
                      float* __restrict__ thresh) {
    int t4 = blockIdx.x * blockDim.x + threadIdx.x;
    int idx = t4 * 4;
    int x = idx & (W_ - 1);
    int y = idx >> LOG2W;
    bool ym = (y > 0), yp = (y < H_ - 1);
    bool xl = (x > 0), xr = (x + 4 < W_);

    const unsigned DYP = 0x00012221u;   // nibble k = dy[k]+1
    const unsigned DXP = 0x21000122u;   // nibble k = dx[k]+1

    const float* b = grad + y * W_ + x;
    float tp[6], md[6], bt[6];
    if (ym) {
        float4 v = __ldg((const float4*)(b - W_));
        tp[1] = v.x; tp[2] = v.y; tp[3] = v.z; tp[4] = v.w;
        tp[0] = xl ? __ldg(b - W_ - 1) : 0.f;
        tp[5] = xr ? __ldg(b - W_ + 4) : 0.f;
    } else {
        tp[0] = tp[1] = tp[2] = tp[3] = tp[4] = tp[5] = 0.f;
    }
    {
        float4 v = __ldg((const float4*)b);
        md[1] = v.x; md[2] = v.y; md[3] = v.z; md[4] = v.w;
        md[0] = xl ? __ldg(b - 1) : 0.f;
        md[5] = xr ? __ldg(b + 4) : 0.f;
    }
    if (yp) {
        float4 v = __ldg((const float4*)(b + W_));
        bt[1] = v.x; bt[2] = v.y; bt[3] = v.z; bt[4] = v.w;
        bt[0] = xl ? __ldg(b + W_ - 1) : 0.f;
        bt[5] = xr ? __ldg(b + W_ + 4) : 0.f;
    } else {
        bt[0] = bt[1] = bt[2] = bt[3] = bt[4] = bt[5] = 0.f;
    }

    unsigned qpack = *(const unsigned*)(g_q + idx);
    float thr = __ldg(thr_p);

    float4 th4, ts4;
    float* thA = (float*)&th4;
    float* tsA = (float*)&ts4;
#pragma unroll
    for (int i = 0; i < 4; ++i) {
        float gm = md[i + 1];
        int q  = (int)((qpack >> (i * 8)) & 0xFFu);
        int kp = q & 7;
        int kn = (q + 4) & 7;

        int dyp = (int)((DYP >> (kp * 4)) & 3u) - 1;
        int dxp = (int)((DXP >> (kp * 4)) & 3u) - 1;
        int dyn = (int)((DYP >> (kn * 4)) & 3u) - 1;
        int dxn = (int)((DXP >> (kn * 4)) & 3u) - 1;

        float tT = (dxp < 0) ? tp[i] : ((dxp > 0) ? tp[i + 2] : tp[i + 1]);
        float tM = (dxp < 0) ? md[i] : ((dxp > 0) ? md[i + 2] : md[i + 1]);
        float tB = (dxp < 0) ? bt[i] : ((dxp > 0) ? bt[i + 2] : bt[i + 1]);
        float np = (dyp < 0) ? tT : ((dyp > 0) ? tB : tM);

        float uT = (dxn < 0) ? tp[i] : ((dxn > 0) ? tp[i + 2] : tp[i + 1]);
        float uM = (dxn < 0) ? md[i] : ((dxn > 0) ? md[i + 2] : md[i + 1]);
        float uB = (dxn < 0) ? bt[i] : ((dxn > 0) ? bt[i + 2] : bt[i + 1]);
        float nn = (dyn < 0) ? uT : ((dyn > 0) ? uB : uM);

        float pos = __fadd_rn(gm, -np);
        float neg = __fadd_rn(gm, -nn);
        float tv = (fminf(pos, neg) > 0.f) ? gm : 0.f;
        thA[i] = tv;
        tsA[i] = (tv < thr) ? 0.f : tv;
    }
    *(float4*)(thin + idx)   = th4;
    *(float4*)(thresh + idx) = ts4;
}

// ---------------------------------------------------------------------------
// Launch
// Inputs: img[3HW], threshold[1], gauss_h[5], gauss_v[5], sobel_h[9],
//         sobel_v[9], dir_w[72]
// Output: [0,3HW) blurred | [3HW,4HW) grad | [4HW,5HW) orient |
//         [5HW,6HW) thin | [6HW,7HW) thresholded | [7HW,8HW) early
// ---------------------------------------------------------------------------
extern "C" void kernel_launch(void* const* d_in, const int* in_sizes, int n_in,
                              void* d_out, int out_size) {
    const float* img   = (const float*)d_in[0];
    const float* thr   = (const float*)d_in[1];
    const float* gauss = (const float*)d_in[2];

    float* out      = (float*)d_out;
    float* blurred  = out;
    float* grad     = out + 3 * HW_;
    float* orient   = out + 4 * HW_;
    float* thin     = out + 5 * HW_;
    float* thresh   = out + 6 * HW_;
    float* early    = out + 7 * HW_;

    dim3 fgrid(W_ / FTX, H_ / FTY);             // 16 x 128
    blur_sobel_k<<<fgrid, 256>>>(img, gauss, thr, blurred, grad, orient, early);

    int blocks1 = (HW_ / 4 + 255) / 256;        // 4096
    nms_k<<<blocks1, 256>>>(grad, thr, thin, thresh);
}

// round 11
// speedup vs baseline: 1.0393x; 1.0393x over previous
#include <cuda_runtime.h>
#include <math.h>

// Problem constants (fixed by reference: H = W = 2048)
#define H_ 2048
#define W_ 2048
#define HW_ (H_ * W_)
#define LOG2W 11

// Packed direction indices (one byte per pixel), sobel -> nms. 4 MB scratch.
__device__ unsigned char g_q[HW_];

// ---------------------------------------------------------------------------
// Kernel 1: fused separable gaussian (1x5 then 5x1, zero pad 2).
// Tile 128x32 per block/channel. Identical to R6/R9 (bit-exact).
// ---------------------------------------------------------------------------
#define TILE_X 128
#define TILE_Y 32
#define SROWS (TILE_Y + 4)
#define TX4 (TILE_X / 4)

__global__ void blur_f_k(const float* __restrict__ img, const float* __restrict__ g,
                         float* __restrict__ blurred) {
    __shared__ float4 sh4[SROWS][TX4];
    const int c = blockIdx.z;
    const int tileX0 = blockIdx.x * TILE_X;
    const int tileY0 = blockIdx.y * TILE_Y;
    const int t = threadIdx.x;          // 0..255
    const float* im = img + c * HW_;
    const float g0 = g[0], g1 = g[1], g2 = g[2], g3 = g[3], g4 = g[4];
    const float4 z4 = make_float4(0.f, 0.f, 0.f, 0.f);

    for (int u = t; u < SROWS * TX4; u += 256) {
        int r   = u >> 5;
        int cx4 = u & 31;
        int gy  = tileY0 - 2 + r;
        float4 o = z4;
        if (gy >= 0 && gy < H_) {
            const float4* row4 = (const float4*)(im + gy * W_);
            int gx = tileX0 + cx4 * 4;
            float4 L = (gx >= 4)     ? __ldg(row4 + (gx >> 2) - 1) : z4;
            float4 M =                 __ldg(row4 + (gx >> 2));
            float4 R = (gx + 4 < W_) ? __ldg(row4 + (gx >> 2) + 1) : z4;
            float v0 = L.z, v1 = L.w;
            float v2 = M.x, v3 = M.y, v4 = M.z, v5 = M.w;
            float v6 = R.x, v7 = R.y;
            o.x = fmaf(g4, v4, fmaf(g3, v3, fmaf(g2, v2, fmaf(g1, v1, __fmul_rn(g0, v0)))));
            o.y = fmaf(g4, v5, fmaf(g3, v4, fmaf(g2, v3, fmaf(g1, v2, __fmul_rn(g0, v1)))));
            o.z = fmaf(g4, v6, fmaf(g3, v5, fmaf(g2, v4, fmaf(g1, v3, __fmul_rn(g0, v2)))));
            o.w = fmaf(g4, v7, fmaf(g3, v6, fmaf(g2, v5, fmaf(g1, v4, __fmul_rn(g0, v3)))));
        }
        sh4[r][cx4] = o;
    }
    __syncthreads();

    {
        int ty0 = (t >> 5) * 4;
        int tx4 = t & 31;
        float4 r0 = sh4[ty0    ][tx4];
        float4 r1 = sh4[ty0 + 1][tx4];
        float4 r2 = sh4[ty0 + 2][tx4];
        float4 r3 = sh4[ty0 + 3][tx4];
        float4 r4 = sh4[ty0 + 4][tx4];
        float4 r5 = sh4[ty0 + 5][tx4];
        float4 r6 = sh4[ty0 + 6][tx4];
        float4 r7 = sh4[ty0 + 7][tx4];
        float* base = blurred + c * HW_ + (tileY0 + ty0) * W_ + tileX0 + tx4 * 4;

#define VBLUR(d, a0, a1, a2, a3, a4)                                                               \
        {                                                                                           \
            float4 o;                                                                               \
            o.x = fmaf(g4, a4.x, fmaf(g3, a3.x, fmaf(g2, a2.x, fmaf(g1, a1.x, __fmul_rn(g0, a0.x))))); \
            o.y = fmaf(g4, a4.y, fmaf(g3, a3.y, fmaf(g2, a2.y, fmaf(g1, a1.y, __fmul_rn(g0, a0.y))))); \
            o.z = fmaf(g4, a4.z, fmaf(g3, a3.z, fmaf(g2, a2.z, fmaf(g1, a1.z, __fmul_rn(g0, a0.z))))); \
            o.w = fmaf(g4, a4.w, fmaf(g3, a3.w, fmaf(g2, a2.w, fmaf(g1, a1.w, __fmul_rn(g0, a0.w))))); \
            *(float4*)(base + (d) * W_) = o;                                                        \
        }
        VBLUR(0, r0, r1, r2, r3, r4)
        VBLUR(1, r1, r2, r3, r4, r5)
        VBLUR(2, r2, r3, r4, r5, r6)
        VBLUR(3, r3, r4, r5, r6, r7)
#undef VBLUR
    }
}

// ---------------------------------------------------------------------------
// Kernel 2: Sobel (zero pad 1) + grad_mag + orient + early_threshold.
// 4 px/thread, plus packed q-byte store. Identical to R9 (bit-exact).
// ---------------------------------------------------------------------------
__global__ void sobel_k(const float* __restrict__ blurred,
                        const float* __restrict__ thr_p,
                        float* __restrict__ grad,
                        float* __restrict__ orient,
                        float* __restrict__ early) {
    int t4 = blockIdx.x * blockDim.x + threadIdx.x;   // float4 index
    int idx = t4 * 4;
    int x = idx & (W_ - 1);
    int y = idx >> LOG2W;
    bool ym = (y > 0), yp = (y < H_ - 1);
    bool xl = (x > 0), xr = (x + 4 < W_);

    float mag[4] = {0.f, 0.f, 0.f, 0.f};
    float sx[4]  = {0.f, 0.f, 0.f, 0.f};
    float sy[4]  = {0.f, 0.f, 0.f, 0.f};

#pragma unroll
    for (int c = 0; c < 3; ++c) {
        const float* b = blurred + c * HW_ + y * W_ + x;
        float tp[6], md[6], bt[6];
        if (ym) {
            float4 v = __ldg((const float4*)(b - W_));
            tp[1] = v.x; tp[2] = v.y; tp[3] = v.z; tp[4] = v.w;
            tp[0] = xl ? __ldg(b - W_ - 1) : 0.f;
            tp[5] = xr ? __ldg(b - W_ + 4) : 0.f;
        } else {
            tp[0] = tp[1] = tp[2] = tp[3] = tp[4] = tp[5] = 0.f;
        }
        {
            float4 v = __ldg((const float4*)b);
            md[1] = v.x; md[2] = v.y; md[3] = v.z; md[4] = v.w;
            md[0] = xl ? __ldg(b - 1) : 0.f;
            md[5] = xr ? __ldg(b + 4) : 0.f;
        }
        if (yp) {
            float4 v = __ldg((const float4*)(b + W_));
            bt[1] = v.x; bt[2] = v.y; bt[3] = v.z; bt[4] = v.w;
            bt[0] = xl ? __ldg(b + W_ - 1) : 0.f;
            bt[5] = xr ? __ldg(b + W_ + 4) : 0.f;
        } else {
            bt[0] = bt[1] = bt[2] = bt[3] = bt[4] = bt[5] = 0.f;
        }
#pragma unroll
        for (int i = 0; i < 4; ++i) {
            float a00 = tp[i], a01 = tp[i + 1], a02 = tp[i + 2];
            float a10 = md[i],                  a12 = md[i + 2];
            float a20 = bt[i], a21 = bt[i + 1], a22 = bt[i + 2];
            float gx = a00;
            gx = fmaf(-1.f, a02, gx);
            gx = fmaf( 2.f, a10, gx);
            gx = fmaf(-2.f, a12, gx);
            gx = fmaf( 1.f, a20, gx);
            gx = fmaf(-1.f, a22, gx);
            float gy = a00;
            gy = fmaf( 2.f, a01, gy);
            gy = fmaf( 1.f, a02, gy);
            gy = fmaf(-1.f, a20, gy);
            gy = fmaf(-2.f, a21, gy);
            gy = fmaf(-1.f, a22, gy);

            mag[i] = __fadd_rn(mag[i], sqrtf(fmaf(gx, gx, __fmul_rn(gy, gy))));
            sx[i]  = __fadd_rn(sx[i], gx);
            sy[i]  = __fadd_rn(sy[i], gy);
        }
    }

    const float C = (float)(180.0 / 3.14159);   // NOTE: 3.14159, not pi
    float thr = __ldg(thr_p);
    float4 gm4, or4, ea4;
    float* gmA = (float*)&gm4;
    float* orA = (float*)&or4;
    float* eaA = (float*)&ea4;
    unsigned qpack = 0;
#pragma unroll
    for (int i = 0; i < 4; ++i) {
        float o  = atan2f(sy[i], sx[i]);         // libdevice __nv_atan2f (same as XLA)
        float ov = __fmul_rn(o, C);
        float tt = __fdiv_rn(__fadd_rn(ov, 180.0f), 45.0f);
        float q  = rintf(tt);                    // half-even (jnp.round)
        gmA[i] = mag[i];
        orA[i] = __fmul_rn(q, 45.0f);
        eaA[i] = (mag[i] < thr) ? 0.f : mag[i];
        qpack |= ((unsigned)(int)q) << (i * 8);  // q in [0,8]
    }
    *(float4*)(grad + idx)   = gm4;
    *(float4*)(orient + idx) = or4;
    *(float4*)(early + idx)  = ea4;
    *(unsigned*)(g_q + idx)  = qpack;
}

// ---------------------------------------------------------------------------
// Kernel 3: NMS + threshold, 8 px/thread.
// Exact reformulation: min(rn(gm-np), rn(gm-nn)) > 0  <=>  gm > max(np, nn),
// and since the two neighbors are point-symmetric (kn = kp+4), max(np,nn) is
// one of 4 pair-maxes selected by q&3:
//   0:(E,W)  1:(SE,NW)  2:(S,N)  3:(SW,NE)
// Zero-filled borders == reference zero padding.
// ---------------------------------------------------------------------------
__global__ void nms_k(const float* __restrict__ grad,
                      const float* __restrict__ thr_p,
                      float* __restrict__ thin,
                      float* __restrict__ thresh) {
    int t8 = blockIdx.x * blockDim.x + threadIdx.x;
    int idx = t8 * 8;
    int x = idx & (W_ - 1);
    int y = idx >> LOG2W;
    bool ym = (y > 0), yp = (y < H_ - 1);
    bool xl = (x > 0), xr = (x + 8 < W_);

    const float* b = grad + y * W_ + x;
    float tp[10], md[10], bt[10];
    if (ym) {
        float4 v0 = __ldg((const float4*)(b - W_));
        float4 v1 = __ldg((const float4*)(b - W_ + 4));
        tp[1] = v0.x; tp[2] = v0.y; tp[3] = v0.z; tp[4] = v0.w;
        tp[5] = v1.x; tp[6] = v1.y; tp[7] = v1.z; tp[8] = v1.w;
        tp[0] = xl ? __ldg(b - W_ - 1) : 0.f;
        tp[9] = xr ? __ldg(b - W_ + 8) : 0.f;
    } else {
#pragma unroll
        for (int j = 0; j < 10; ++j) tp[j] = 0.f;
    }
    {
        float4 v0 = __ldg((const float4*)b);
        float4 v1 = __ldg((const float4*)(b + 4));
        md[1] = v0.x; md[2] = v0.y; md[3] = v0.z; md[4] = v0.w;
        md[5] = v1.x; md[6] = v1.y; md[7] = v1.z; md[8] = v1.w;
        md[0] = xl ? __ldg(b - 1) : 0.f;
        md[9] = xr ? __ldg(b + 8) : 0.f;
    }
    if (yp) {
        float4 v0 = __ldg((const float4*)(b + W_));
        float4 v1 = __ldg((const float4*)(b + W_ + 4));
        bt[1] = v0.x; bt[2] = v0.y; bt[3] = v0.z; bt[4] = v0.w;
        bt[5] = v1.x; bt[6] = v1.y; bt[7] = v1.z; bt[8] = v1.w;
        bt[0] = xl ? __ldg(b + W_ - 1) : 0.f;
        bt[9] = xr ? __ldg(b + W_ + 8) : 0.f;
    } else {
#pragma unroll
        for (int j = 0; j < 10; ++j) bt[j] = 0.f;
    }

    uint2 qp = *(const uint2*)(g_q + idx);
    float thr = __ldg(thr_p);

    float4 th4a, th4b, ts4a, ts4b;
    float* thA = (float*)&th4a;    // [0..3] then th4b
    float* tsA = (float*)&ts4a;
#pragma unroll
    for (int i = 0; i < 8; ++i) {
        float gm = md[i + 1];
        unsigned qb = (i < 4) ? (qp.x >> (i * 8)) : (qp.y >> ((i - 4) * 8));
        int p = (int)(qb & 3u);    // pair index (q=8 -> 0, correct)

        float pm0 = fmaxf(md[i + 2], md[i]);       // E , W
        float pm1 = fmaxf(bt[i + 2], tp[i]);       // SE, NW
        float pm2 = fmaxf(bt[i + 1], tp[i + 1]);   // S , N
        float pm3 = fmaxf(bt[i],     tp[i + 2]);   // SW, NE
        float pm = (p < 2) ? ((p == 0) ? pm0 : pm1)
                           : ((p == 2) ? pm2 : pm3);

        float tv = (gm > pm) ? gm : 0.f;
        float ts = (tv < thr) ? 0.f : tv;
        if (i < 4) { thA[i] = tv; tsA[i] = ts; }
        else       { ((float*)&th4b)[i - 4] = tv; ((float*)&ts4b)[i - 4] = ts; }
    }
    *(float4*)(thin + idx)       = th4a;
    *(float4*)(thin + idx + 4)   = th4b;
    *(float4*)(thresh + idx)     = ts4a;
    *(float4*)(thresh + idx + 4) = ts4b;
}

// ---------------------------------------------------------------------------
// Launch
// Inputs: img[3HW], threshold[1], gauss_h[5], gauss_v[5], sobel_h[9],
//         sobel_v[9], dir_w[72]
// Output: [0,3HW) blurred | [3HW,4HW) grad | [4HW,5HW) orient |
//         [5HW,6HW) thin | [6HW,7HW) thresholded | [7HW,8HW) early
// ---------------------------------------------------------------------------
extern "C" void kernel_launch(void* const* d_in, const int* in_sizes, int n_in,
                              void* d_out, int out_size) {
    const float* img   = (const float*)d_in[0];
    const float* thr   = (const float*)d_in[1];
    const float* gauss = (const float*)d_in[2];

    float* out      = (float*)d_out;
    float* blurred  = out;
    float* grad     = out + 3 * HW_;
    float* orient   = out + 4 * HW_;
    float* thin     = out + 5 * HW_;
    float* thresh   = out + 6 * HW_;
    float* early    = out + 7 * HW_;

    dim3 bgrid(W_ / TILE_X, H_ / TILE_Y, 3);   // 16 x 64 x 3
    blur_f_k<<<bgrid, 256>>>(img, gauss, blurred);

    int blocks4 = (HW_ / 4 + 255) / 256;        // 4096
    sobel_k<<<blocks4, 256>>>(blurred, thr, grad, orient, early);

    int blocks8 = (HW_ / 8 + 255) / 256;        // 2048
    nms_k<<<blocks8, 256>>>(grad, thr, thin, thresh);
}

// round 12
// speedup vs baseline: 1.0750x; 1.0344x over previous
#include <cuda_runtime.h>
#include <math.h>

// Problem constants (fixed by reference: H = W = 2048)
#define H_ 2048
#define W_ 2048
#define HW_ (H_ * W_)
#define LOG2W 11

// Packed direction indices (one byte per pixel), sobel -> nms. 4 MB scratch.
__device__ unsigned char g_q[HW_];

// ---------------------------------------------------------------------------
// Kernel 1: fused separable gaussian (1x5 then 5x1, zero pad 2).
// Tile 128x32 per block/channel. Identical to R6/R9 (bit-exact).
// ---------------------------------------------------------------------------
#define TILE_X 128
#define TILE_Y 32
#define SROWS (TILE_Y + 4)
#define TX4 (TILE_X / 4)

__global__ void blur_f_k(const float* __restrict__ img, const float* __restrict__ g,
                         float* __restrict__ blurred) {
    __shared__ float4 sh4[SROWS][TX4];
    const int c = blockIdx.z;
    const int tileX0 = blockIdx.x * TILE_X;
    const int tileY0 = blockIdx.y * TILE_Y;
    const int t = threadIdx.x;          // 0..255
    const float* im = img + c * HW_;
    const float g0 = g[0], g1 = g[1], g2 = g[2], g3 = g[3], g4 = g[4];
    const float4 z4 = make_float4(0.f, 0.f, 0.f, 0.f);

    for (int u = t; u < SROWS * TX4; u += 256) {
        int r   = u >> 5;
        int cx4 = u & 31;
        int gy  = tileY0 - 2 + r;
        float4 o = z4;
        if (gy >= 0 && gy < H_) {
            const float4* row4 = (const float4*)(im + gy * W_);
            int gx = tileX0 + cx4 * 4;
            float4 L = (gx >= 4)     ? __ldg(row4 + (gx >> 2) - 1) : z4;
            float4 M =                 __ldg(row4 + (gx >> 2));
            float4 R = (gx + 4 < W_) ? __ldg(row4 + (gx >> 2) + 1) : z4;
            float v0 = L.z, v1 = L.w;
            float v2 = M.x, v3 = M.y, v4 = M.z, v5 = M.w;
            float v6 = R.x, v7 = R.y;
            o.x = fmaf(g4, v4, fmaf(g3, v3, fmaf(g2, v2, fmaf(g1, v1, __fmul_rn(g0, v0)))));
            o.y = fmaf(g4, v5, fmaf(g3, v4, fmaf(g2, v3, fmaf(g1, v2, __fmul_rn(g0, v1)))));
            o.z = fmaf(g4, v6, fmaf(g3, v5, fmaf(g2, v4, fmaf(g1, v3, __fmul_rn(g0, v2)))));
            o.w = fmaf(g4, v7, fmaf(g3, v6, fmaf(g2, v5, fmaf(g1, v4, __fmul_rn(g0, v3)))));
        }
        sh4[r][cx4] = o;
    }
    __syncthreads();

    {
        int ty0 = (t >> 5) * 4;
        int tx4 = t & 31;
        float4 r0 = sh4[ty0    ][tx4];
        float4 r1 = sh4[ty0 + 1][tx4];
        float4 r2 = sh4[ty0 + 2][tx4];
        float4 r3 = sh4[ty0 + 3][tx4];
        float4 r4 = sh4[ty0 + 4][tx4];
        float4 r5 = sh4[ty0 + 5][tx4];
        float4 r6 = sh4[ty0 + 6][tx4];
        float4 r7 = sh4[ty0 + 7][tx4];
        float* base = blurred + c * HW_ + (tileY0 + ty0) * W_ + tileX0 + tx4 * 4;

#define VBLUR(d, a0, a1, a2, a3, a4)                                                               \
        {                                                                                           \
            float4 o;                                                                               \
            o.x = fmaf(g4, a4.x, fmaf(g3, a3.x, fmaf(g2, a2.x, fmaf(g1, a1.x, __fmul_rn(g0, a0.x))))); \
            o.y = fmaf(g4, a4.y, fmaf(g3, a3.y, fmaf(g2, a2.y, fmaf(g1, a1.y, __fmul_rn(g0, a0.y))))); \
            o.z = fmaf(g4, a4.z, fmaf(g3, a3.z, fmaf(g2, a2.z, fmaf(g1, a1.z, __fmul_rn(g0, a0.z))))); \
            o.w = fmaf(g4, a4.w, fmaf(g3, a3.w, fmaf(g2, a2.w, fmaf(g1, a1.w, __fmul_rn(g0, a0.w))))); \
            *(float4*)(base + (d) * W_) = o;                                                        \
        }
        VBLUR(0, r0, r1, r2, r3, r4)
        VBLUR(1, r1, r2, r3, r4, r5)
        VBLUR(2, r2, r3, r4, r5, r6)
        VBLUR(3, r3, r4, r5, r6, r7)
#undef VBLUR
    }
}

// ---------------------------------------------------------------------------
// Kernel 2: Sobel (zero pad 1) + grad_mag + orient + early_threshold.
// 4 px/thread, plus packed q-byte store. Identical to R9 (bit-exact).
// ---------------------------------------------------------------------------
__global__ void sobel_k(const float* __restrict__ blurred,
                        const float* __restrict__ thr_p,
                        float* __restrict__ grad,
                        float* __restrict__ orient,
                        float* __restrict__ early) {
    int t4 = blockIdx.x * blockDim.x + threadIdx.x;   // float4 index
    int idx = t4 * 4;
    int x = idx & (W_ - 1);
    int y = idx >> LOG2W;
    bool ym = (y > 0), yp = (y < H_ - 1);
    bool xl = (x > 0), xr = (x + 4 < W_);

    float mag[4] = {0.f, 0.f, 0.f, 0.f};
    float sx[4]  = {0.f, 0.f, 0.f, 0.f};
    float sy[4]  = {0.f, 0.f, 0.f, 0.f};

#pragma unroll
    for (int c = 0; c < 3; ++c) {
        const float* b = blurred + c * HW_ + y * W_ + x;
        float tp[6], md[6], bt[6];
        if (ym) {
            float4 v = __ldg((const float4*)(b - W_));
            tp[1] = v.x; tp[2] = v.y; tp[3] = v.z; tp[4] = v.w;
            tp[0] = xl ? __ldg(b - W_ - 1) : 0.f;
            tp[5] = xr ? __ldg(b - W_ + 4) : 0.f;
        } else {
            tp[0] = tp[1] = tp[2] = tp[3] = tp[4] = tp[5] = 0.f;
        }
        {
            float4 v = __ldg((const float4*)b);
            md[1] = v.x; md[2] = v.y; md[3] = v.z; md[4] = v.w;
            md[0] = xl ? __ldg(b - 1) : 0.f;
            md[5] = xr ? __ldg(b + 4) : 0.f;
        }
        if (yp) {
            float4 v = __ldg((const float4*)(b + W_));
            bt[1] = v.x; bt[2] = v.y; bt[3] = v.z; bt[4] = v.w;
            bt[0] = xl ? __ldg(b + W_ - 1) : 0.f;
            bt[5] = xr ? __ldg(b + W_ + 4) : 0.f;
        } else {
            bt[0] = bt[1] = bt[2] = bt[3] = bt[4] = bt[5] = 0.f;
        }
#pragma unroll
        for (int i = 0; i < 4; ++i) {
            float a00 = tp[i], a01 = tp[i + 1], a02 = tp[i + 2];
            float a10 = md[i],                  a12 = md[i + 2];
            float a20 = bt[i], a21 = bt[i + 1], a22 = bt[i + 2];
            float gx = a00;
            gx = fmaf(-1.f, a02, gx);
            gx = fmaf( 2.f, a10, gx);
            gx = fmaf(-2.f, a12, gx);
            gx = fmaf( 1.f, a20, gx);
            gx = fmaf(-1.f, a22, gx);
            float gy = a00;
            gy = fmaf( 2.f, a01, gy);
            gy = fmaf( 1.f, a02, gy);
            gy = fmaf(-1.f, a20, gy);
            gy = fmaf(-2.f, a21, gy);
            gy = fmaf(-1.f, a22, gy);

            mag[i] = __fadd_rn(mag[i], sqrtf(fmaf(gx, gx, __fmul_rn(gy, gy))));
            sx[i]  = __fadd_rn(sx[i], gx);
            sy[i]  = __fadd_rn(sy[i], gy);
        }
    }

    const float C = (float)(180.0 / 3.14159);   // NOTE: 3.14159, not pi
    float thr = __ldg(thr_p);
    float4 gm4, or4, ea4;
    float* gmA = (float*)&gm4;
    float* orA = (float*)&or4;
    float* eaA = (float*)&ea4;
    unsigned qpack = 0;
#pragma unroll
    for (int i = 0; i < 4; ++i) {
        float o  = atan2f(sy[i], sx[i]);         // libdevice __nv_atan2f (same as XLA)
        float ov = __fmul_rn(o, C);
        float tt = __fdiv_rn(__fadd_rn(ov, 180.0f), 45.0f);
        float q  = rintf(tt);                    // half-even (jnp.round)
        gmA[i] = mag[i];
        orA[i] = __fmul_rn(q, 45.0f);
        eaA[i] = (mag[i] < thr) ? 0.f : mag[i];
        qpack |= ((unsigned)(int)q) << (i * 8);  // q in [0,8]
    }
    *(float4*)(grad + idx)   = gm4;
    *(float4*)(orient + idx) = or4;
    *(float4*)(early + idx)  = ea4;
    *(unsigned*)(g_q + idx)  = qpack;
}

// ---------------------------------------------------------------------------
// Kernel 3: NMS + threshold, 4 px/thread (R9 footprint) with the exact
// pair-max reformulation:
//   min(rn(gm-np), rn(gm-nn)) > 0  <=>  gm > np && gm > nn  <=>  gm > max(np,nn)
// (f32 subtraction is sign-exact). Neighbors are point-symmetric (kn = kp+4),
// so max(np,nn) is one of 4 pair-maxes selected by q&3:
//   0:(E,W)  1:(SE,NW)  2:(S,N)  3:(SW,NE)     (q=8 -> 0, correct)
// Zero-filled borders == reference zero padding.
// ---------------------------------------------------------------------------
__global__ void nms_k(const float* __restrict__ grad,
                      const float* __restrict__ thr_p,
                      float* __restrict__ thin,
                      float* __restrict__ thresh) {
    int t4 = blockIdx.x * blockDim.x + threadIdx.x;
    int idx = t4 * 4;
    int x = idx & (W_ - 1);
    int y = idx >> LOG2W;
    bool ym = (y > 0), yp = (y < H_ - 1);
    bool xl = (x > 0), xr = (x + 4 < W_);

    const float* b = grad + y * W_ + x;
    float tp[6], md[6], bt[6];
    if (ym) {
        float4 v = __ldg((const float4*)(b - W_));
        tp[1] = v.x; tp[2] = v.y; tp[3] = v.z; tp[4] = v.w;
        tp[0] = xl ? __ldg(b - W_ - 1) : 0.f;
        tp[5] = xr ? __ldg(b - W_ + 4) : 0.f;
    } else {
        tp[0] = tp[1] = tp[2] = tp[3] = tp[4] = tp[5] = 0.f;
    }
    {
        float4 v = __ldg((const float4*)b);
        md[1] = v.x; md[2] = v.y; md[3] = v.z; md[4] = v.w;
        md[0] = xl ? __ldg(b - 1) : 0.f;
        md[5] = xr ? __ldg(b + 4) : 0.f;
    }
    if (yp) {
        float4 v = __ldg((const float4*)(b + W_));
        bt[1] = v.x; bt[2] = v.y; bt[3] = v.z; bt[4] = v.w;
        bt[0] = xl ? __ldg(b + W_ - 1) : 0.f;
        bt[5] = xr ? __ldg(b + W_ + 4) : 0.f;
    } else {
        bt[0] = bt[1] = bt[2] = bt[3] = bt[4] = bt[5] = 0.f;
    }

    unsigned qpack = *(const unsigned*)(g_q + idx);
    float thr = __ldg(thr_p);

    float4 th4, ts4;
    float* thA = (float*)&th4;
    float* tsA = (float*)&ts4;
#pragma unroll
    for (int i = 0; i < 4; ++i) {
        float gm = md[i + 1];
        int p = (int)((qpack >> (i * 8)) & 3u);   // pair index

        float pm0 = fmaxf(md[i + 2], md[i]);       // E , W
        float pm1 = fmaxf(bt[i + 2], tp[i]);       // SE, NW
        float pm2 = fmaxf(bt[i + 1], tp[i + 1]);   // S , N
        float pm3 = fmaxf(bt[i],     tp[i + 2]);   // SW, NE
        float pm = (p < 2) ? ((p == 0) ? pm0 : pm1)
                           : ((p == 2) ? pm2 : pm3);

        float tv = (gm > pm) ? gm : 0.f;
        thA[i] = tv;
        tsA[i] = (tv < thr) ? 0.f : tv;
    }
    *(float4*)(thin + idx)   = th4;
    *(float4*)(thresh + idx) = ts4;
}

// ---------------------------------------------------------------------------
// Launch
// Inputs: img[3HW], threshold[1], gauss_h[5], gauss_v[5], sobel_h[9],
//         sobel_v[9], dir_w[72]
// Output: [0,3HW) blurred | [3HW,4HW) grad | [4HW,5HW) orient |
//         [5HW,6HW) thin | [6HW,7HW) thresholded | [7HW,8HW) early
// ---------------------------------------------------------------------------
extern "C" void kernel_launch(void* const* d_in, const int* in_sizes, int n_in,
                              void* d_out, int out_size) {
    const float* img   = (const float*)d_in[0];
    const float* thr   = (const float*)d_in[1];
    const float* gauss = (const float*)d_in[2];

    float* out      = (float*)d_out;
    float* blurred  = out;
    float* grad     = out + 3 * HW_;
    float* orient   = out + 4 * HW_;
    float* thin     = out + 5 * HW_;
    float* thresh   = out + 6 * HW_;
    float* early    = out + 7 * HW_;

    dim3 bgrid(W_ / TILE_X, H_ / TILE_Y, 3);   // 16 x 64 x 3
    blur_f_k<<<bgrid, 256>>>(img, gauss, blurred);

    int blocks4 = (HW_ / 4 + 255) / 256;        // 4096
    sobel_k<<<blocks4, 256>>>(blurred, thr, grad, orient, early);
    nms_k<<<blocks4, 256>>>(grad, thr, thin, thresh);
}